// round 3
// baseline (speedup 1.0000x reference)
#include <cuda_runtime.h>
#include <math.h>

#define HIDDEN   128
#define NPTS_MAX 1024
#define N_TABLE  416
#define TABLE_ELEMS (N_TABLE * HIDDEN)

// a_indices = theta * 180/(15*pi) = theta * 12/pi
#define FACTOR_A 3.8197186342054885f
#define PI_F     3.14159265358979323846f

// Precomputed output table: g_table[t*HIDDEN + h] = f_h(theta_t), theta_t = pi*t/(N_TABLE-1)
__device__ float g_table[TABLE_ELEMS];

// ---------------------------------------------------------------------------
// Kernel 1: build the lookup table. One block per theta sample, 128 threads.
// thread h computes f_h(theta_t) = b[h] + sum_k emb[k] * W[h*128 + k]
// emb[2k] = sin(a_idx * w_k), emb[2k+1] = cos(a_idx * w_k), w_k = 10000^(-k/64)
// ---------------------------------------------------------------------------
__global__ void build_table_kernel(const float* __restrict__ W,
                                   const float* __restrict__ b) {
    __shared__ float emb[HIDDEN];
    const int t = blockIdx.x;
    const int h = threadIdx.x;

    const float theta = PI_F * (float)t / (float)(N_TABLE - 1);
    const float a_idx = theta * FACTOR_A;

    if (h < 64) {
        // div_term[k] = exp(-k * ln(10000)/64)
        const float kexp = -(float)h * (9.210340371976184f / 64.0f);
        const float w_k = expf(kexp);
        float s, c;
        sincosf(a_idx * w_k, &s, &c);
        emb[2 * h]     = s;
        emb[2 * h + 1] = c;
    }
    __syncthreads();

    float acc = b[h];
    const float* Wrow = W + h * HIDDEN;
#pragma unroll 8
    for (int k = 0; k < HIDDEN; k++) {
        acc = fmaf(emb[k], Wrow[k], acc);
    }
    g_table[t * HIDDEN + h] = acc;
}

// ---------------------------------------------------------------------------
// Kernel 2: main pair kernel. One block per point i (grid = n), 512 threads.
// Table (208 KB) + normals SoA (12 KB) live in shared memory.
// Each warp handles one pair (i,j) per iteration:
//   - all lanes compute theta (SIMT: redundancy across lanes is free)
//   - lane l lerps 4 output channels (float4) between table rows i0 and i0+1
//   - coalesced 512B float4 store per pair
// ---------------------------------------------------------------------------
__global__ void __launch_bounds__(512, 1)
pair_embed_kernel(const float* __restrict__ normals,
                  float* __restrict__ out,
                  int n) {
    extern __shared__ float smem[];
    float* s_table = smem;                       // TABLE_ELEMS floats
    float* s_nx = smem + TABLE_ELEMS;            // n floats
    float* s_ny = s_nx + NPTS_MAX;
    float* s_nz = s_ny + NPTS_MAX;

    // Cooperative load of the table (float4 vectorized)
    {
        const float4* src = (const float4*)g_table;
        float4* dst = (float4*)s_table;
        for (int idx = threadIdx.x; idx < TABLE_ELEMS / 4; idx += blockDim.x)
            dst[idx] = src[idx];
    }
    // Normals as SoA for broadcast LDS
    for (int j = threadIdx.x; j < n; j += blockDim.x) {
        s_nx[j] = normals[3 * j + 0];
        s_ny[j] = normals[3 * j + 1];
        s_nz[j] = normals[3 * j + 2];
    }
    __syncthreads();

    const int i = blockIdx.x;
    const int warp = threadIdx.x >> 5;
    const int lane = threadIdx.x & 31;
    const int nwarps = blockDim.x >> 5;

    const float ax = s_nx[i], ay = s_ny[i], az = s_nz[i];
    const float scale = (float)(N_TABLE - 1) / PI_F;

    for (int j = warp; j < n; j += nwarps) {
        const float bx = s_nx[j], by = s_ny[j], bz = s_nz[j];

        // cross(a, b), |cross|, dot
        const float cx = ay * bz - az * by;
        const float cy = az * bx - ax * bz;
        const float cz = ax * by - ay * bx;
        const float sv = sqrtf(cx * cx + cy * cy + cz * cz);
        const float cv = ax * bx + ay * by + az * bz;

        const float theta = atan2f(sv, cv);   // in [0, pi]
        float tf = theta * scale;
        int i0 = (int)tf;
        if (i0 > N_TABLE - 2) i0 = N_TABLE - 2;
        const float w = tf - (float)i0;

        const float4* r0 = (const float4*)(s_table + i0 * HIDDEN);
        const float4* r1 = (const float4*)(s_table + (i0 + 1) * HIDDEN);
        const float4 a4 = r0[lane];
        const float4 b4 = r1[lane];

        float4 o;
        o.x = fmaf(w, b4.x - a4.x, a4.x);
        o.y = fmaf(w, b4.y - a4.y, a4.y);
        o.z = fmaf(w, b4.z - a4.z, a4.z);
        o.w = fmaf(w, b4.w - a4.w, a4.w);

        float4* dst = (float4*)(out + ((size_t)i * (size_t)n + (size_t)j) * HIDDEN);
        dst[lane] = o;
    }
}

extern "C" void kernel_launch(void* const* d_in, const int* in_sizes, int n_in,
                              void* d_out, int out_size) {
    // Inputs (metadata order): points, normals, W, b
    const float* normals = (const float*)d_in[1];
    const float* W       = (const float*)d_in[2];
    const float* b       = (const float*)d_in[3];
    float* out = (float*)d_out;

    const int n = in_sizes[1] / 3;   // 1024

    build_table_kernel<<<N_TABLE, HIDDEN>>>(W, b);

    const size_t smem_bytes = (size_t)(TABLE_ELEMS + 3 * NPTS_MAX) * sizeof(float);
    cudaFuncSetAttribute(pair_embed_kernel,
                         cudaFuncAttributeMaxDynamicSharedMemorySize,
                         (int)smem_bytes);
    pair_embed_kernel<<<n, 512, smem_bytes>>>(normals, out, n);
}

// round 8
// speedup vs baseline: 1.0022x; 1.0022x over previous
#include <cuda_runtime.h>
#include <math.h>

#define HIDDEN   128
#define NPTS_MAX 1024
#define N_TABLE  416
#define TABLE_ELEMS (N_TABLE * HIDDEN)

// a_indices = theta * 180/(15*pi) = theta * 12/pi
#define FACTOR_A 3.8197186342054885f
#define PI_F     3.14159265358979323846f

// Precomputed output table: g_table[t*HIDDEN + h] = f_h(theta_t), theta_t = pi*t/(N_TABLE-1)
__device__ float g_table[TABLE_ELEMS];

// ---------------------------------------------------------------------------
// Kernel 1: build the lookup table. One block per theta sample, 128 threads.
// thread h computes f_h(theta_t) = b[h] + sum_k emb[k] * W[h*128 + k]
// emb[2k] = sin(a_idx * w_k), emb[2k+1] = cos(a_idx * w_k), w_k = 10000^(-k/64)
// ---------------------------------------------------------------------------
__global__ void build_table_kernel(const float* __restrict__ W,
                                   const float* __restrict__ b) {
    __shared__ float emb[HIDDEN];
    const int t = blockIdx.x;
    const int h = threadIdx.x;

    const float theta = PI_F * (float)t / (float)(N_TABLE - 1);
    const float a_idx = theta * FACTOR_A;

    if (h < 64) {
        // div_term[k] = exp(-k * ln(10000)/64)
        const float kexp = -(float)h * (9.210340371976184f / 64.0f);
        const float w_k = expf(kexp);
        float s, c;
        sincosf(a_idx * w_k, &s, &c);
        emb[2 * h]     = s;
        emb[2 * h + 1] = c;
    }
    __syncthreads();

    float acc = b[h];
    const float* Wrow = W + h * HIDDEN;
#pragma unroll 8
    for (int k = 0; k < HIDDEN; k++) {
        acc = fmaf(emb[k], Wrow[k], acc);
    }
    g_table[t * HIDDEN + h] = acc;
}

// ---------------------------------------------------------------------------
// Kernel 2: main pair kernel. One block per point i (grid = n), 512 threads.
// Table (208 KB) + normals SoA (12 KB) live in shared memory.
// Each warp handles one pair (i,j) per iteration:
//   - all lanes compute theta (SIMT: redundancy across lanes is free)
//   - lane l lerps 4 output channels (float4) between table rows i0 and i0+1
//   - coalesced 512B float4 store per pair
// ---------------------------------------------------------------------------
__global__ void __launch_bounds__(512, 1)
pair_embed_kernel(const float* __restrict__ normals,
                  float* __restrict__ out,
                  int n) {
    extern __shared__ float smem[];
    float* s_table = smem;                       // TABLE_ELEMS floats
    float* s_nx = smem + TABLE_ELEMS;            // n floats
    float* s_ny = s_nx + NPTS_MAX;
    float* s_nz = s_ny + NPTS_MAX;

    // Cooperative load of the table (float4 vectorized)
    {
        const float4* src = (const float4*)g_table;
        float4* dst = (float4*)s_table;
        for (int idx = threadIdx.x; idx < TABLE_ELEMS / 4; idx += blockDim.x)
            dst[idx] = src[idx];
    }
    // Normals as SoA for broadcast LDS
    for (int j = threadIdx.x; j < n; j += blockDim.x) {
        s_nx[j] = normals[3 * j + 0];
        s_ny[j] = normals[3 * j + 1];
        s_nz[j] = normals[3 * j + 2];
    }
    __syncthreads();

    const int i = blockIdx.x;
    const int warp = threadIdx.x >> 5;
    const int lane = threadIdx.x & 31;
    const int nwarps = blockDim.x >> 5;

    const float ax = s_nx[i], ay = s_ny[i], az = s_nz[i];
    const float scale = (float)(N_TABLE - 1) / PI_F;

    for (int j = warp; j < n; j += nwarps) {
        const float bx = s_nx[j], by = s_ny[j], bz = s_nz[j];

        // cross(a, b), |cross|, dot
        const float cx = ay * bz - az * by;
        const float cy = az * bx - ax * bz;
        const float cz = ax * by - ay * bx;
        const float sv = sqrtf(cx * cx + cy * cy + cz * cz);
        const float cv = ax * bx + ay * by + az * bz;

        const float theta = atan2f(sv, cv);   // in [0, pi]
        float tf = theta * scale;
        int i0 = (int)tf;
        if (i0 > N_TABLE - 2) i0 = N_TABLE - 2;
        const float w = tf - (float)i0;

        const float4* r0 = (const float4*)(s_table + i0 * HIDDEN);
        const float4* r1 = (const float4*)(s_table + (i0 + 1) * HIDDEN);
        const float4 a4 = r0[lane];
        const float4 b4 = r1[lane];

        float4 o;
        o.x = fmaf(w, b4.x - a4.x, a4.x);
        o.y = fmaf(w, b4.y - a4.y, a4.y);
        o.z = fmaf(w, b4.z - a4.z, a4.z);
        o.w = fmaf(w, b4.w - a4.w, a4.w);

        float4* dst = (float4*)(out + ((size_t)i * (size_t)n + (size_t)j) * HIDDEN);
        dst[lane] = o;
    }
}

extern "C" void kernel_launch(void* const* d_in, const int* in_sizes, int n_in,
                              void* d_out, int out_size) {
    // Inputs (metadata order): points, normals, W, b
    const float* normals = (const float*)d_in[1];
    const float* W       = (const float*)d_in[2];
    const float* b       = (const float*)d_in[3];
    float* out = (float*)d_out;

    const int n = in_sizes[1] / 3;   // 1024

    build_table_kernel<<<N_TABLE, HIDDEN>>>(W, b);

    const size_t smem_bytes = (size_t)(TABLE_ELEMS + 3 * NPTS_MAX) * sizeof(float);
    cudaFuncSetAttribute(pair_embed_kernel,
                         cudaFuncAttributeMaxDynamicSharedMemorySize,
                         (int)smem_bytes);
    pair_embed_kernel<<<n, 512, smem_bytes>>>(normals, out, n);
}